// round 3
// baseline (speedup 1.0000x reference)
#include <cuda_runtime.h>
#include <cuda_bf16.h>

#define B 512
#define T 512
#define C 96
#define SUBS 4              // batch elements per CTA
#define FWD_THREADS (SUBS * C)   // 384

__device__ float g_den[B];
__device__ float g_num[B];
__device__ int   g_tags_is32;     // 1 if tags buffer is int32, 0 if int64
__device__ int   g_mask_stride;   // bytes per mask element: 1 (bool/int8) or 4 (int32)

__device__ __forceinline__ unsigned long long pack2(float lo, float hi) {
    unsigned long long r;
    asm("mov.b64 %0, {%1, %2};" : "=l"(r) : "f"(lo), "f"(hi));
    return r;
}
__device__ __forceinline__ void unpack2(unsigned long long v, float& lo, float& hi) {
    asm("mov.b64 {%0, %1}, %2;" : "=f"(lo), "=f"(hi) : "l"(v));
}
__device__ __forceinline__ unsigned long long ffma2(unsigned long long a,
                                                    unsigned long long b,
                                                    unsigned long long c) {
    unsigned long long d;
    asm("fma.rn.f32x2 %0, %1, %2, %3;" : "=l"(d) : "l"(a), "l"(b), "l"(c));
    return d;
}
__device__ __forceinline__ unsigned long long fadd2(unsigned long long a,
                                                    unsigned long long b) {
    unsigned long long d;
    asm("add.rn.f32x2 %0, %1, %2;" : "=l"(d) : "l"(a), "l"(b));
    return d;
}

// Detect input encodings.
// tags: JAX w/o x64 silently stores int64-requested tags as int32. If true int64
//       (values 0..95, little endian), every odd 32-bit word is 0.
// mask: harness may widen bool->int32. If stored as bytes (0/1), 32-bit words of an
//       all/mostly-true mask exceed 1 (e.g. 0x01010101); int32 words are always 0/1.
__global__ void crf_detect_kernel(const int* __restrict__ t32,
                                  const unsigned int* __restrict__ mw)
{
    __shared__ int tag_any, mask_byte;
    if (threadIdx.x == 0) { tag_any = 0; mask_byte = 0; }
    __syncthreads();
    if (t32[threadIdx.x * 2 + 1] != 0) tag_any = 1;          // benign same-value race
    for (int i = threadIdx.x; i < 2048; i += blockDim.x)
        if (mw[i] > 1u) mask_byte = 1;
    __syncthreads();
    if (threadIdx.x == 0) {
        g_tags_is32   = tag_any;
        g_mask_stride = mask_byte ? 1 : 4;
    }
}

// Forward algorithm. 4 batch elements per CTA (sub = tid/96, thread j = state j).
// E column exp(trans[:, j]) lives in 48 packed f32x2 registers. Per step:
//   p_i = exp(alpha_i - m)  (m = thread-0 alpha from previous step; exact lse shift)
//   new_alpha_j = emit_j + m + log( sum_i p_i * E[i][j] )
// One barrier per step via double-buffered sh_p.
__global__ void __launch_bounds__(FWD_THREADS, 1) crf_forward_kernel(
    const float* __restrict__ emissions,
    const unsigned char* __restrict__ mask,
    const float* __restrict__ start_t,
    const float* __restrict__ end_t,
    const float* __restrict__ trans)
{
    const int tid  = threadIdx.x;
    const int sub  = tid / C;          // 0..3  (96 = 3 warps: aligns with warp bounds)
    const int j    = tid - sub * C;    // 0..95
    const int wsub = j >> 5;           // warp index within sub: 0..2
    const int lane = j & 31;
    const int b    = blockIdx.x * SUBS + sub;
    const int ms   = g_mask_stride;

    __shared__ __align__(16) float sh_p[2][SUBS][C];
    __shared__ float sh_m[2][SUBS];
    __shared__ float sh_r[SUBS][4];

    // E column j, packed in pairs: E2[k] = { exp(trans[2k][j]), exp(trans[2k+1][j]) }
    unsigned long long E2[C / 2];
    {
        const float* tb = trans + j;
#pragma unroll
        for (int k = 0; k < C / 2; k++) {
            const float lo = __expf(tb[(2 * k) * C]);
            const float hi = __expf(tb[(2 * k + 1) * C]);
            E2[k] = pack2(lo, hi);
        }
    }

    const float* em = emissions + (size_t)b * T * C + j;
    const unsigned char* mk = mask + (size_t)b * T * ms;

    float alpha = start_t[j] + em[0];
    // lse shift = alpha of state 0 (computable by every thread, no broadcast needed)
    float m = start_t[0] + emissions[(size_t)b * T * C];

    // prefetch distance 2
    float e1 = em[C];
    float e2 = em[2 * (size_t)C];
    unsigned char k1 = mk[1 * ms];
    unsigned char k2 = mk[2 * ms];

    int buf = 0;
    for (int t = 1; t < T; t++, buf ^= 1) {
        sh_p[buf][sub][j] = __expf(alpha - m);
        if (j == 0) sh_m[buf][sub] = alpha;      // next step's shift
        __syncthreads();

        // acc = sum_i p_i * E[i]   (packed f32x2 FMAs; LDS.128 is a warp broadcast)
        const ulonglong2* p2 = (const ulonglong2*)sh_p[buf][sub];
        unsigned long long a0 = 0ull, a1 = 0ull;
#pragma unroll
        for (int i = 0; i < C / 4; i++) {
            const ulonglong2 v = p2[i];
            a0 = ffma2(v.x, E2[2 * i + 0], a0);
            a1 = ffma2(v.y, E2[2 * i + 1], a1);
        }
        float lo, hi;
        unpack2(fadd2(a0, a1), lo, hi);
        const float acc = lo + hi;

        const float e_cur = e1;
        const unsigned char mc = k1;
        e1 = e2; k1 = k2;
        if (t + 2 < T) {
            e2 = em[(size_t)(t + 2) * C];
            k2 = mk[(size_t)(t + 2) * ms];
        }

        const float na = e_cur + m + __logf(acc);
        alpha = mc ? na : alpha;
        m = sh_m[buf][sub];                      // thread-0 alpha, 1 step stale
    }

    // log_den[b] = logsumexp_j(alpha_j + end_j)
    const float v = alpha + end_t[j];
    float wm = v;
    wm = fmaxf(wm, __shfl_xor_sync(0xffffffffu, wm, 16));
    wm = fmaxf(wm, __shfl_xor_sync(0xffffffffu, wm, 8));
    wm = fmaxf(wm, __shfl_xor_sync(0xffffffffu, wm, 4));
    wm = fmaxf(wm, __shfl_xor_sync(0xffffffffu, wm, 2));
    wm = fmaxf(wm, __shfl_xor_sync(0xffffffffu, wm, 1));
    if (lane == 0) sh_r[sub][wsub] = wm;
    __syncthreads();
    const float mf = fmaxf(fmaxf(sh_r[sub][0], sh_r[sub][1]), sh_r[sub][2]);
    __syncthreads();

    float pv = __expf(v - mf);
    pv += __shfl_xor_sync(0xffffffffu, pv, 16);
    pv += __shfl_xor_sync(0xffffffffu, pv, 8);
    pv += __shfl_xor_sync(0xffffffffu, pv, 4);
    pv += __shfl_xor_sync(0xffffffffu, pv, 2);
    pv += __shfl_xor_sync(0xffffffffu, pv, 1);
    if (lane == 0) sh_r[sub][wsub] = pv;
    __syncthreads();
    if (j == 0) {
        const float s = sh_r[sub][0] + sh_r[sub][1] + sh_r[sub][2];
        g_den[b] = mf + __logf(s);
    }
}

// Numerator (path score): one CTA per batch element.
__global__ void __launch_bounds__(128) crf_score_kernel(
    const float* __restrict__ emissions,
    const void* __restrict__ tags_raw,
    const unsigned char* __restrict__ mask,
    const float* __restrict__ start_t,
    const float* __restrict__ end_t,
    const float* __restrict__ trans)
{
    const int b = blockIdx.x;
    const int tid = threadIdx.x;
    const int is32 = g_tags_is32;
    const int ms = g_mask_stride;

    const int* tg32 = (const int*)tags_raw + (size_t)b * T;
    const long long* tg64 = (const long long*)tags_raw + (size_t)b * T;
    const unsigned char* mk = mask + (size_t)b * T * ms;
    const float* eb = emissions + (size_t)b * T * C;

    float s = 0.f;
    int len = 0;
    for (int t = tid; t < T; t += 128) {
        const int mt = mk[(size_t)t * ms] ? 1 : 0;
        len += mt;
        if (t >= 1 && mt) {
            const int ct = is32 ? tg32[t] : (int)tg64[t];
            const int pt = is32 ? tg32[t - 1] : (int)tg64[t - 1];
            s += eb[(size_t)t * C + ct] + trans[pt * C + ct];
        }
    }

    __shared__ float rs[128];
    __shared__ int   rl[128];
    rs[tid] = s;
    rl[tid] = len;
    __syncthreads();
#pragma unroll
    for (int off = 64; off > 0; off >>= 1) {
        if (tid < off) { rs[tid] += rs[tid + off]; rl[tid] += rl[tid + off]; }
        __syncthreads();
    }
    if (tid == 0) {
        const int t0    = is32 ? tg32[0] : (int)tg64[0];
        const int tlast = is32 ? tg32[rl[0] - 1] : (int)tg64[rl[0] - 1];
        g_num[b] = rs[0] + start_t[t0] + eb[t0] + end_t[tlast];
    }
}

// Mean over batch of (log_den - log_num).
__global__ void __launch_bounds__(512) crf_final_kernel(float* __restrict__ out)
{
    const int tid = threadIdx.x;
    __shared__ float r[512];
    r[tid] = g_den[tid] - g_num[tid];
    __syncthreads();
#pragma unroll
    for (int off = 256; off > 0; off >>= 1) {
        if (tid < off) r[tid] += r[tid + off];
        __syncthreads();
    }
    if (tid == 0) out[0] = r[0] * (1.0f / (float)B);
}

extern "C" void kernel_launch(void* const* d_in, const int* in_sizes, int n_in,
                              void* d_out, int out_size)
{
    const float*         emissions = (const float*)d_in[0];
    const void*          tags      = d_in[1];
    const unsigned char* mask      = (const unsigned char*)d_in[2];
    const float*         start_t   = (const float*)d_in[3];
    const float*         end_t     = (const float*)d_in[4];
    const float*         trans     = (const float*)d_in[5];
    float* out = (float*)d_out;

    crf_detect_kernel<<<1, 256>>>((const int*)tags, (const unsigned int*)mask);
    crf_forward_kernel<<<B / SUBS, FWD_THREADS>>>(emissions, mask, start_t, end_t, trans);
    crf_score_kernel<<<B, 128>>>(emissions, tags, mask, start_t, end_t, trans);
    crf_final_kernel<<<1, 512>>>(out);
}

// round 4
// speedup vs baseline: 1.0494x; 1.0494x over previous
#include <cuda_runtime.h>
#include <cuda_bf16.h>

#define B 512
#define T 512
#define C 96

__device__ float g_den[B];
__device__ float g_num[B];
__device__ int   g_tags_is32;      // 1 if tags buffer is int32, 0 if int64
__device__ int   g_mask_stride;    // bytes per mask element: 1 or 4
__device__ int   g_mask_allones;   // 1 if every mask element is true

__device__ __forceinline__ void unpack2(unsigned long long v, float& lo, float& hi) {
    asm("mov.b64 {%0, %1}, %2;" : "=f"(lo), "=f"(hi) : "l"(v));
}
__device__ __forceinline__ unsigned long long pack2(float lo, float hi) {
    unsigned long long r;
    asm("mov.b64 %0, {%1, %2};" : "=l"(r) : "f"(lo), "f"(hi));
    return r;
}
__device__ __forceinline__ unsigned long long ffma2(unsigned long long a,
                                                    unsigned long long b,
                                                    unsigned long long c) {
    unsigned long long d;
    asm("fma.rn.f32x2 %0, %1, %2, %3;" : "=l"(d) : "l"(a), "l"(b), "l"(c));
    return d;
}
__device__ __forceinline__ unsigned long long fadd2(unsigned long long a,
                                                    unsigned long long b) {
    unsigned long long d;
    asm("add.rn.f32x2 %0, %1, %2;" : "=l"(d) : "l"(a), "l"(b));
    return d;
}
__device__ __forceinline__ float frcp_fast(float x) {
    float r;
    asm("rcp.approx.f32 %0, %1;" : "=f"(r) : "f"(x));
    return r;
}
__device__ __forceinline__ void bar_sub(int id) {
    asm volatile("bar.sync %0, %1;" :: "r"(id), "r"(192) : "memory");
}

// ---------------------------------------------------------------------------
// Input-encoding detection (single CTA).
// tags:  JAX w/o x64 stores int64-requested tags as int32 (odd words all 0 => int64)
// mask:  bool may be stored as bytes or widened to int32. Any word > 1 => bytes.
//        all-ones: bytes => every word 0x01010101; int32 => every word 1.
__global__ void __launch_bounds__(1024) crf_detect_kernel(
    const int* __restrict__ t32, const unsigned int* __restrict__ mw)
{
    __shared__ int tag_any, mask_byte, not_ones_b, not_ones_w;
    const int tid = threadIdx.x;
    if (tid == 0) { tag_any = 0; mask_byte = 0; not_ones_b = 0; not_ones_w = 0; }
    __syncthreads();
    for (int i = tid; i < 512; i += 1024)
        if (t32[i * 2 + 1] != 0) tag_any = 1;
    for (int i = tid; i < 65536; i += 1024) {            // first 256 KB (full byte mask)
        const unsigned int v = mw[i];
        if (v > 1u) mask_byte = 1;
        if (v != 0x01010101u) not_ones_b = 1;
        if (v != 1u) not_ones_w = 1;
    }
    __syncthreads();
    int nw = 0;
    if (!mask_byte) {                                    // int32 mask: scan the rest
        for (int i = 65536 + tid; i < 262144; i += 1024)
            if (mw[i] != 1u) nw = 1;
    }
    if (nw) not_ones_w = 1;
    __syncthreads();
    if (tid == 0) {
        g_tags_is32   = tag_any;
        g_mask_stride = mask_byte ? 1 : 4;
        g_mask_allones = mask_byte ? !not_ones_b : !not_ones_w;
    }
}

// ---------------------------------------------------------------------------
// FAST forward (mask all ones): linear-space recurrence.
//   u_{t+1,j} = (sum_i u_t[i] * E[i][j]) * exp(emit_{t+1,j}) * inv_c
// with c = u_t[0] (bounded within ~1e-3 of max) and s += log(1/inv_c) off-path.
// 2 subs/CTA, 2 threads per state (48-term halves, shfl combine), named barriers.
__global__ void __launch_bounds__(384, 2) crf_forward_fast_kernel(
    const float* __restrict__ emissions,
    const float* __restrict__ start_t,
    const float* __restrict__ end_t,
    const float* __restrict__ trans)
{
    if (!g_mask_allones) return;

    const int tid = threadIdx.x;
    const int sub = tid / 192;          // 0..1
    const int ts  = tid - sub * 192;    // 0..191
    const int j   = ts >> 1;            // state 0..95
    const int h   = ts & 1;             // half 0..1
    const int b   = blockIdx.x * 2 + sub;
    const int wsub = ts >> 5;           // warp within sub 0..5

    __shared__ __align__(16) float sh_u[2][2][C];
    __shared__ float sh_c[2][2];
    __shared__ float sh_r[2][6];

    // E rows [h*48, h*48+48) of column j, packed f32x2 (24 u64 regs)
    unsigned long long E2[24];
    {
        const float* tb = trans + (size_t)(h * 48) * C + j;
#pragma unroll
        for (int k = 0; k < 24; k++) {
            const float lo = __expf(tb[(2 * k) * C]);
            const float hi = __expf(tb[(2 * k + 1) * C]);
            E2[k] = pack2(lo, hi);
        }
    }

    const float* em = emissions + (size_t)b * T * C + j;

    // t = 0 init: u = exp(alpha0 - alpha0[0]); s = alpha0[0]
    const float a00 = start_t[0] + emissions[(size_t)b * T * C];
    float s = a00;
    {
        const float u0 = __expf(start_t[j] + em[0] - a00);
        if (h == 0) sh_u[0][sub][j] = u0;
        if (ts == 0) sh_c[0][sub] = 1.0f;   // u[0] = exp(0)
    }

    float ee1e  = __expf(em[C]);            // exp(emit) for t=1
    float eraw2 = em[2 * (size_t)C];        // raw emit for t=2

    bar_sub(sub + 1);

    int buf = 0;
    for (int t = 1; t < T; t++) {
        const float c   = sh_c[buf][sub];
        const float inv = frcp_fast(c);
        const float fac = ee1e * inv;

        const ulonglong2* p2 = (const ulonglong2*)(sh_u[buf][sub] + h * 48);
        unsigned long long a0 = 0ull, a1 = 0ull, a2 = 0ull, a3 = 0ull;
#pragma unroll
        for (int k = 0; k < 6; k++) {
            const ulonglong2 v0 = p2[2 * k];
            const ulonglong2 v1 = p2[2 * k + 1];
            a0 = ffma2(v0.x, E2[4 * k + 0], a0);
            a1 = ffma2(v0.y, E2[4 * k + 1], a1);
            a2 = ffma2(v1.x, E2[4 * k + 2], a2);
            a3 = ffma2(v1.y, E2[4 * k + 3], a3);
        }
        float lo, hi;
        unpack2(fadd2(fadd2(a0, a1), fadd2(a2, a3)), lo, hi);
        float acc = lo + hi;                                  // 48-term half
        acc += __shfl_xor_sync(0xffffffffu, acc, 1);          // full 96-term

        const float un = acc * fac;

        // rotate emission prefetch (off critical path)
        ee1e = __expf(eraw2);
        if (t + 2 < T) eraw2 = em[(size_t)(t + 2) * C];

        const int nbuf = buf ^ 1;
        if (h == 0) sh_u[nbuf][sub][j] = un;
        if (ts == 0) { sh_c[nbuf][sub] = un; s -= __logf(inv); }
        bar_sub(sub + 1);
        buf = nbuf;
    }

    // log_den[b] = s + log( sum_j u[j] * exp(end[j]) )
    float part = (h == 0) ? sh_u[buf][sub][j] * __expf(end_t[j]) : 0.0f;
    part += __shfl_xor_sync(0xffffffffu, part, 1);
    part += __shfl_xor_sync(0xffffffffu, part, 2);
    part += __shfl_xor_sync(0xffffffffu, part, 4);
    part += __shfl_xor_sync(0xffffffffu, part, 8);
    part += __shfl_xor_sync(0xffffffffu, part, 16);
    if ((ts & 31) == 0) sh_r[sub][wsub] = part;
    bar_sub(sub + 1);
    if (ts == 0) {
        float tot = 0.f;
#pragma unroll
        for (int w = 0; w < 6; w++) tot += sh_r[sub][w];
        g_den[b] = s + __logf(tot);
    }
}

// ---------------------------------------------------------------------------
// FALLBACK forward (general mask): log-space, shifted lse (R3 version).
__global__ void __launch_bounds__(384, 1) crf_forward_gen_kernel(
    const float* __restrict__ emissions,
    const unsigned char* __restrict__ mask,
    const float* __restrict__ start_t,
    const float* __restrict__ end_t,
    const float* __restrict__ trans)
{
    if (g_mask_allones) return;

    const int tid  = threadIdx.x;
    const int sub  = tid / C;
    const int j    = tid - sub * C;
    const int wsub = j >> 5;
    const int lane = j & 31;
    const int b    = blockIdx.x * 4 + sub;
    const int ms   = g_mask_stride;

    __shared__ __align__(16) float sh_p[2][4][C];
    __shared__ float sh_m[2][4];
    __shared__ float sh_r[4][4];

    unsigned long long E2[C / 2];
    {
        const float* tb = trans + j;
#pragma unroll
        for (int k = 0; k < C / 2; k++)
            E2[k] = pack2(__expf(tb[(2 * k) * C]), __expf(tb[(2 * k + 1) * C]));
    }

    const float* em = emissions + (size_t)b * T * C + j;
    const unsigned char* mk = mask + (size_t)b * T * ms;

    float alpha = start_t[j] + em[0];
    float m = start_t[0] + emissions[(size_t)b * T * C];

    float e1 = em[C];
    float e2 = em[2 * (size_t)C];
    unsigned char k1 = mk[1 * ms];
    unsigned char k2 = mk[2 * ms];

    int buf = 0;
    for (int t = 1; t < T; t++, buf ^= 1) {
        sh_p[buf][sub][j] = __expf(alpha - m);
        if (j == 0) sh_m[buf][sub] = alpha;
        __syncthreads();

        const ulonglong2* p2 = (const ulonglong2*)sh_p[buf][sub];
        unsigned long long a0 = 0ull, a1 = 0ull;
#pragma unroll
        for (int i = 0; i < C / 4; i++) {
            const ulonglong2 v = p2[i];
            a0 = ffma2(v.x, E2[2 * i + 0], a0);
            a1 = ffma2(v.y, E2[2 * i + 1], a1);
        }
        float lo, hi;
        unpack2(fadd2(a0, a1), lo, hi);
        const float acc = lo + hi;

        const float e_cur = e1;
        const unsigned char mc = k1;
        e1 = e2; k1 = k2;
        if (t + 2 < T) { e2 = em[(size_t)(t + 2) * C]; k2 = mk[(size_t)(t + 2) * ms]; }

        const float na = e_cur + m + __logf(acc);
        alpha = mc ? na : alpha;
        m = sh_m[buf][sub];
    }

    const float v = alpha + end_t[j];
    float wm = v;
    wm = fmaxf(wm, __shfl_xor_sync(0xffffffffu, wm, 16));
    wm = fmaxf(wm, __shfl_xor_sync(0xffffffffu, wm, 8));
    wm = fmaxf(wm, __shfl_xor_sync(0xffffffffu, wm, 4));
    wm = fmaxf(wm, __shfl_xor_sync(0xffffffffu, wm, 2));
    wm = fmaxf(wm, __shfl_xor_sync(0xffffffffu, wm, 1));
    if (lane == 0) sh_r[sub][wsub] = wm;
    __syncthreads();
    const float mf = fmaxf(fmaxf(sh_r[sub][0], sh_r[sub][1]), sh_r[sub][2]);
    __syncthreads();

    float pv = __expf(v - mf);
    pv += __shfl_xor_sync(0xffffffffu, pv, 16);
    pv += __shfl_xor_sync(0xffffffffu, pv, 8);
    pv += __shfl_xor_sync(0xffffffffu, pv, 4);
    pv += __shfl_xor_sync(0xffffffffu, pv, 2);
    pv += __shfl_xor_sync(0xffffffffu, pv, 1);
    if (lane == 0) sh_r[sub][wsub] = pv;
    __syncthreads();
    if (j == 0)
        g_den[b] = mf + __logf(sh_r[sub][0] + sh_r[sub][1] + sh_r[sub][2]);
}

// ---------------------------------------------------------------------------
// Numerator (path score): one CTA per batch element.
__global__ void __launch_bounds__(128) crf_score_kernel(
    const float* __restrict__ emissions,
    const void* __restrict__ tags_raw,
    const unsigned char* __restrict__ mask,
    const float* __restrict__ start_t,
    const float* __restrict__ end_t,
    const float* __restrict__ trans)
{
    const int b = blockIdx.x;
    const int tid = threadIdx.x;
    const int is32 = g_tags_is32;
    const int ms = g_mask_stride;

    const int* tg32 = (const int*)tags_raw + (size_t)b * T;
    const long long* tg64 = (const long long*)tags_raw + (size_t)b * T;
    const unsigned char* mk = mask + (size_t)b * T * ms;
    const float* eb = emissions + (size_t)b * T * C;

    float sacc = 0.f;
    int len = 0;
    for (int t = tid; t < T; t += 128) {
        const int mt = mk[(size_t)t * ms] ? 1 : 0;
        len += mt;
        if (t >= 1 && mt) {
            const int ct = is32 ? tg32[t] : (int)tg64[t];
            const int pt = is32 ? tg32[t - 1] : (int)tg64[t - 1];
            sacc += eb[(size_t)t * C + ct] + trans[pt * C + ct];
        }
    }

    __shared__ float rs[128];
    __shared__ int   rl[128];
    rs[tid] = sacc;
    rl[tid] = len;
    __syncthreads();
#pragma unroll
    for (int off = 64; off > 0; off >>= 1) {
        if (tid < off) { rs[tid] += rs[tid + off]; rl[tid] += rl[tid + off]; }
        __syncthreads();
    }
    if (tid == 0) {
        const int t0    = is32 ? tg32[0] : (int)tg64[0];
        const int tlast = is32 ? tg32[rl[0] - 1] : (int)tg64[rl[0] - 1];
        g_num[b] = rs[0] + start_t[t0] + eb[t0] + end_t[tlast];
    }
}

// Mean over batch of (log_den - log_num).
__global__ void __launch_bounds__(512) crf_final_kernel(float* __restrict__ out)
{
    const int tid = threadIdx.x;
    __shared__ float r[512];
    r[tid] = g_den[tid] - g_num[tid];
    __syncthreads();
#pragma unroll
    for (int off = 256; off > 0; off >>= 1) {
        if (tid < off) r[tid] += r[tid + off];
        __syncthreads();
    }
    if (tid == 0) out[0] = r[0] * (1.0f / (float)B);
}

extern "C" void kernel_launch(void* const* d_in, const int* in_sizes, int n_in,
                              void* d_out, int out_size)
{
    const float*         emissions = (const float*)d_in[0];
    const void*          tags      = d_in[1];
    const unsigned char* mask      = (const unsigned char*)d_in[2];
    const float*         start_t   = (const float*)d_in[3];
    const float*         end_t     = (const float*)d_in[4];
    const float*         trans     = (const float*)d_in[5];
    float* out = (float*)d_out;

    crf_detect_kernel<<<1, 1024>>>((const int*)tags, (const unsigned int*)mask);
    crf_forward_fast_kernel<<<B / 2, 384>>>(emissions, start_t, end_t, trans);
    crf_forward_gen_kernel<<<B / 4, 384>>>(emissions, mask, start_t, end_t, trans);
    crf_score_kernel<<<B, 128>>>(emissions, tags, mask, start_t, end_t, trans);
    crf_final_kernel<<<1, 512>>>(out);
}

// round 5
// speedup vs baseline: 1.0638x; 1.0138x over previous
#include <cuda_runtime.h>
#include <cuda_bf16.h>

#define B 512
#define T 512
#define C 96

__device__ float g_den[B];
__device__ float g_num[B];
__device__ int g_tag_any;      // any odd 32-bit word nonzero => tags are int32
__device__ int g_mask_byte;    // any mask word > 1 => mask stored as bytes
__device__ int g_not_ones_b;   // (byte mask) some word != 0x01010101
__device__ int g_not_ones_w;   // (int32 mask) some word != 1

__device__ __forceinline__ void unpack2(unsigned long long v, float& lo, float& hi) {
    asm("mov.b64 {%0, %1}, %2;" : "=f"(lo), "=f"(hi) : "l"(v));
}
__device__ __forceinline__ unsigned long long pack2(float lo, float hi) {
    unsigned long long r;
    asm("mov.b64 %0, {%1, %2};" : "=l"(r) : "f"(lo), "f"(hi));
    return r;
}
__device__ __forceinline__ unsigned long long ffma2(unsigned long long a,
                                                    unsigned long long b,
                                                    unsigned long long c) {
    unsigned long long d;
    asm("fma.rn.f32x2 %0, %1, %2, %3;" : "=l"(d) : "l"(a), "l"(b), "l"(c));
    return d;
}
__device__ __forceinline__ unsigned long long fadd2(unsigned long long a,
                                                    unsigned long long b) {
    unsigned long long d;
    asm("add.rn.f32x2 %0, %1, %2;" : "=l"(d) : "l"(a), "l"(b));
    return d;
}
__device__ __forceinline__ float frcp_fast(float x) {
    float r;
    asm("rcp.approx.f32 %0, %1;" : "=f"(r) : "f"(x));
    return r;
}
__device__ __forceinline__ void bar_sub(int id) {
    asm volatile("bar.sync %0, %1;" :: "r"(id), "r"(192) : "memory");
}

// ---------------------------------------------------------------------------
// Detection. init (1 thread) -> scanA (safe first 256KB + tags) -> scanB
// (remaining 768KB, only if mask is int32-typed).
__global__ void crf_init_kernel()
{
    g_tag_any = 0; g_mask_byte = 0; g_not_ones_b = 0; g_not_ones_w = 0;
}

__global__ void __launch_bounds__(256) crf_detect_a_kernel(
    const int* __restrict__ t32, const unsigned int* __restrict__ mw)
{
    const int gt = blockIdx.x * 256 + threadIdx.x;
    int ta = 0, mb = 0, nb = 0, nw = 0;
    for (int i = gt; i < 512; i += 64 * 256)
        if (t32[i * 2 + 1] != 0) ta = 1;
    for (int i = gt; i < 65536; i += 64 * 256) {   // first 256 KB: full byte-mask span
        const unsigned int v = mw[i];
        if (v > 1u) mb = 1;
        if (v != 0x01010101u) nb = 1;
        if (v != 1u) nw = 1;
    }
    if (ta) atomicOr(&g_tag_any, 1);
    if (mb) atomicOr(&g_mask_byte, 1);
    if (nb) atomicOr(&g_not_ones_b, 1);
    if (nw) atomicOr(&g_not_ones_w, 1);
}

__global__ void __launch_bounds__(256) crf_detect_b_kernel(
    const unsigned int* __restrict__ mw)
{
    if (g_mask_byte) return;                       // byte mask: buffer is only 256 KB
    const int gt = blockIdx.x * 256 + threadIdx.x;
    int nw = 0;
    for (int i = 65536 + gt; i < 262144; i += 64 * 256)
        if (mw[i] != 1u) nw = 1;
    if (nw) atomicOr(&g_not_ones_w, 1);
}

// ---------------------------------------------------------------------------
// FAST forward (mask all ones): linear-space recurrence.
//   u_t[j] = (sum_i u_{t-1}[i] * E[i][j]) * exp(emit_t[j]) / c_t,  c_t = u_{t-1}[0]
// log(c_t) accumulation deferred to a parallel post-loop reduction (history in
// shared), so the per-step critical path is bar -> LDS -> FMA tree -> shfl ->
// FMUL -> STS -> bar. 2 subs/CTA, 2 threads/state, named barriers per sub.
__global__ void __launch_bounds__(384, 2) crf_forward_fast_kernel(
    const float* __restrict__ emissions,
    const float* __restrict__ start_t,
    const float* __restrict__ end_t,
    const float* __restrict__ trans)
{
    const int allones = g_mask_byte ? !g_not_ones_b : !g_not_ones_w;
    if (!allones) return;

    const int tid = threadIdx.x;
    const int sub = tid / 192;          // 0..1
    const int ts  = tid - sub * 192;    // 0..191
    const int j   = ts >> 1;            // state 0..95
    const int h   = ts & 1;             // half 0..1
    const int b   = blockIdx.x * 2 + sub;
    const int wsub = ts >> 5;           // warp within sub 0..5

    __shared__ __align__(16) float sh_u[2][2][C];
    __shared__ float sh_hist[2][T];
    __shared__ float sh_r[2][6][2];

    // E rows [h*48, h*48+48) of column j, packed f32x2 (24 u64 regs)
    unsigned long long E2[24];
    {
        const float* tb = trans + (size_t)(h * 48) * C + j;
#pragma unroll
        for (int k = 0; k < 24; k++)
            E2[k] = pack2(__expf(tb[(2 * k) * C]), __expf(tb[(2 * k + 1) * C]));
    }

    const float* em = emissions + (size_t)b * T * C + j;
    const float a00 = start_t[0] + emissions[(size_t)b * T * C];
    if (h == 0) sh_u[0][sub][j] = __expf(start_t[j] + em[0] - a00);   // u0[0]=1

    float ee1  = __expf(em[C]);             // exp(emit) for t=1
    float er2  = em[2 * (size_t)C];         // raw emit for t=2

    bar_sub(sub + 1);

    int buf = 0;
    for (int t = 1; t < T; t++) {
        const float c   = sh_u[buf][sub][0];        // broadcast LDS.32
        const float inv = frcp_fast(c);             // overlaps the dot
        if (ts == 0) sh_hist[sub][t] = c;           // off critical path

        const ulonglong2* p2 = (const ulonglong2*)(sh_u[buf][sub] + h * 48);
        unsigned long long a0 = 0ull, a1 = 0ull, a2 = 0ull, a3 = 0ull;
#pragma unroll
        for (int k = 0; k < 6; k++) {
            const ulonglong2 v0 = p2[2 * k];
            const ulonglong2 v1 = p2[2 * k + 1];
            a0 = ffma2(v0.x, E2[4 * k + 0], a0);
            a1 = ffma2(v0.y, E2[4 * k + 1], a1);
            a2 = ffma2(v1.x, E2[4 * k + 2], a2);
            a3 = ffma2(v1.y, E2[4 * k + 3], a3);
        }
        float lo, hi;
        unpack2(fadd2(fadd2(a0, a1), fadd2(a2, a3)), lo, hi);
        float acc = lo + hi;                                  // 48-term half
        acc += __shfl_xor_sync(0xffffffffu, acc, 1);          // full 96-term

        const float un = acc * (ee1 * inv);

        // rotate emission prefetch (off critical path)
        ee1 = __expf(er2);
        er2 = (t + 2 < T) ? em[(size_t)(t + 2) * C] : 0.0f;

        if (h == 0) sh_u[buf ^ 1][sub][j] = un;
        buf ^= 1;
        bar_sub(sub + 1);
    }

    // log_den[b] = a00 + sum_t log(c_t) + log( sum_j u_T[j] * exp(end[j]) )
    float pe = (h == 0) ? sh_u[buf][sub][j] * __expf(end_t[j]) : 0.0f;
    float pl = 0.0f;
    for (int tt = 1 + ts; tt < T; tt += 192) pl += __logf(sh_hist[sub][tt]);
#pragma unroll
    for (int off = 16; off > 0; off >>= 1) {
        pe += __shfl_xor_sync(0xffffffffu, pe, off);
        pl += __shfl_xor_sync(0xffffffffu, pl, off);
    }
    if ((ts & 31) == 0) { sh_r[sub][wsub][0] = pe; sh_r[sub][wsub][1] = pl; }
    bar_sub(sub + 1);
    if (ts == 0) {
        float te = 0.f, tl = 0.f;
#pragma unroll
        for (int w = 0; w < 6; w++) { te += sh_r[sub][w][0]; tl += sh_r[sub][w][1]; }
        g_den[b] = a00 + tl + __logf(te);
    }
}

// ---------------------------------------------------------------------------
// FALLBACK forward (general mask): log-space, shifted lse.
__global__ void __launch_bounds__(384, 1) crf_forward_gen_kernel(
    const float* __restrict__ emissions,
    const unsigned char* __restrict__ mask,
    const float* __restrict__ start_t,
    const float* __restrict__ end_t,
    const float* __restrict__ trans)
{
    const int allones = g_mask_byte ? !g_not_ones_b : !g_not_ones_w;
    if (allones) return;

    const int tid  = threadIdx.x;
    const int sub  = tid / C;
    const int j    = tid - sub * C;
    const int wsub = j >> 5;
    const int lane = j & 31;
    const int b    = blockIdx.x * 4 + sub;
    const int ms   = g_mask_byte ? 1 : 4;

    __shared__ __align__(16) float sh_p[2][4][C];
    __shared__ float sh_m[2][4];
    __shared__ float sh_r[4][4];

    unsigned long long E2[C / 2];
    {
        const float* tb = trans + j;
#pragma unroll
        for (int k = 0; k < C / 2; k++)
            E2[k] = pack2(__expf(tb[(2 * k) * C]), __expf(tb[(2 * k + 1) * C]));
    }

    const float* em = emissions + (size_t)b * T * C + j;
    const unsigned char* mk = mask + (size_t)b * T * ms;

    float alpha = start_t[j] + em[0];
    float m = start_t[0] + emissions[(size_t)b * T * C];

    float e1 = em[C];
    float e2 = em[2 * (size_t)C];
    unsigned char k1 = mk[1 * ms];
    unsigned char k2 = mk[2 * ms];

    int buf = 0;
    for (int t = 1; t < T; t++, buf ^= 1) {
        sh_p[buf][sub][j] = __expf(alpha - m);
        if (j == 0) sh_m[buf][sub] = alpha;
        __syncthreads();

        const ulonglong2* p2 = (const ulonglong2*)sh_p[buf][sub];
        unsigned long long a0 = 0ull, a1 = 0ull;
#pragma unroll
        for (int i = 0; i < C / 4; i++) {
            const ulonglong2 v = p2[i];
            a0 = ffma2(v.x, E2[2 * i + 0], a0);
            a1 = ffma2(v.y, E2[2 * i + 1], a1);
        }
        float lo, hi;
        unpack2(fadd2(a0, a1), lo, hi);
        const float acc = lo + hi;

        const float e_cur = e1;
        const unsigned char mc = k1;
        e1 = e2; k1 = k2;
        if (t + 2 < T) { e2 = em[(size_t)(t + 2) * C]; k2 = mk[(size_t)(t + 2) * ms]; }

        const float na = e_cur + m + __logf(acc);
        alpha = mc ? na : alpha;
        m = sh_m[buf][sub];
    }

    const float v = alpha + end_t[j];
    float wm = v;
    wm = fmaxf(wm, __shfl_xor_sync(0xffffffffu, wm, 16));
    wm = fmaxf(wm, __shfl_xor_sync(0xffffffffu, wm, 8));
    wm = fmaxf(wm, __shfl_xor_sync(0xffffffffu, wm, 4));
    wm = fmaxf(wm, __shfl_xor_sync(0xffffffffu, wm, 2));
    wm = fmaxf(wm, __shfl_xor_sync(0xffffffffu, wm, 1));
    if (lane == 0) sh_r[sub][wsub] = wm;
    __syncthreads();
    const float mf = fmaxf(fmaxf(sh_r[sub][0], sh_r[sub][1]), sh_r[sub][2]);
    __syncthreads();

    float pv = __expf(v - mf);
    pv += __shfl_xor_sync(0xffffffffu, pv, 16);
    pv += __shfl_xor_sync(0xffffffffu, pv, 8);
    pv += __shfl_xor_sync(0xffffffffu, pv, 4);
    pv += __shfl_xor_sync(0xffffffffu, pv, 2);
    pv += __shfl_xor_sync(0xffffffffu, pv, 1);
    if (lane == 0) sh_r[sub][wsub] = pv;
    __syncthreads();
    if (j == 0)
        g_den[b] = mf + __logf(sh_r[sub][0] + sh_r[sub][1] + sh_r[sub][2]);
}

// ---------------------------------------------------------------------------
// Numerator (path score): one CTA per batch element.
__global__ void __launch_bounds__(128) crf_score_kernel(
    const float* __restrict__ emissions,
    const void* __restrict__ tags_raw,
    const unsigned char* __restrict__ mask,
    const float* __restrict__ start_t,
    const float* __restrict__ end_t,
    const float* __restrict__ trans)
{
    const int b = blockIdx.x;
    const int tid = threadIdx.x;
    const int is32 = g_tag_any;
    const int ms = g_mask_byte ? 1 : 4;

    const int* tg32 = (const int*)tags_raw + (size_t)b * T;
    const long long* tg64 = (const long long*)tags_raw + (size_t)b * T;
    const unsigned char* mk = mask + (size_t)b * T * ms;
    const float* eb = emissions + (size_t)b * T * C;

    float sacc = 0.f;
    int len = 0;
    for (int t = tid; t < T; t += 128) {
        const int mt = mk[(size_t)t * ms] ? 1 : 0;
        len += mt;
        if (t >= 1 && mt) {
            const int ct = is32 ? tg32[t] : (int)tg64[t];
            const int pt = is32 ? tg32[t - 1] : (int)tg64[t - 1];
            sacc += eb[(size_t)t * C + ct] + trans[pt * C + ct];
        }
    }

    __shared__ float rs[128];
    __shared__ int   rl[128];
    rs[tid] = sacc;
    rl[tid] = len;
    __syncthreads();
#pragma unroll
    for (int off = 64; off > 0; off >>= 1) {
        if (tid < off) { rs[tid] += rs[tid + off]; rl[tid] += rl[tid + off]; }
        __syncthreads();
    }
    if (tid == 0) {
        const int t0    = is32 ? tg32[0] : (int)tg64[0];
        const int tlast = is32 ? tg32[rl[0] - 1] : (int)tg64[rl[0] - 1];
        g_num[b] = rs[0] + start_t[t0] + eb[t0] + end_t[tlast];
    }
}

// Mean over batch of (log_den - log_num).
__global__ void __launch_bounds__(512) crf_final_kernel(float* __restrict__ out)
{
    const int tid = threadIdx.x;
    __shared__ float r[512];
    r[tid] = g_den[tid] - g_num[tid];
    __syncthreads();
#pragma unroll
    for (int off = 256; off > 0; off >>= 1) {
        if (tid < off) r[tid] += r[tid + off];
        __syncthreads();
    }
    if (tid == 0) out[0] = r[0] * (1.0f / (float)B);
}

extern "C" void kernel_launch(void* const* d_in, const int* in_sizes, int n_in,
                              void* d_out, int out_size)
{
    const float*         emissions = (const float*)d_in[0];
    const void*          tags      = d_in[1];
    const unsigned char* mask      = (const unsigned char*)d_in[2];
    const float*         start_t   = (const float*)d_in[3];
    const float*         end_t     = (const float*)d_in[4];
    const float*         trans     = (const float*)d_in[5];
    float* out = (float*)d_out;

    crf_init_kernel<<<1, 1>>>();
    crf_detect_a_kernel<<<64, 256>>>((const int*)tags, (const unsigned int*)mask);
    crf_detect_b_kernel<<<64, 256>>>((const unsigned int*)mask);
    crf_forward_fast_kernel<<<B / 2, 384>>>(emissions, start_t, end_t, trans);
    crf_forward_gen_kernel<<<B / 4, 384>>>(emissions, mask, start_t, end_t, trans);
    crf_score_kernel<<<B, 128>>>(emissions, tags, mask, start_t, end_t, trans);
    crf_final_kernel<<<1, 512>>>(out);
}